// round 7
// baseline (speedup 1.0000x reference)
#include <cuda_runtime.h>
#include <cuda_fp16.h>
#include <math.h>
#include <stdint.h>

#define K_CODES 1024
#define C_DIM   64
#define N_TOT   32768
#define TILE_N  64
#define CHUNK_K 64
#define N_CHUNKS 16
#define N_BLOCKS (N_TOT / TILE_N)   // 512

#define Q_ELEMS  (32*64*32*32)      // 2097152
#define LOSS_OFF Q_ELEMS
#define IDX_OFF  (Q_ELEMS + 1)
#define PERP_OFF (Q_ELEMS + 1 + N_TOT)

#define PITCH_B   144               // 9 x 16B: conflict-free ldmatrix rows
#define PLANE_A   9216              // 64 rows x 144 B (x planes)
#define PLANE_BB  9216              // 64 rows x 144 B (B planes)

// smem layout (dynamic)
#define OFF_SXH   0
#define OFF_SXL   (OFF_SXH + PLANE_A)
#define OFF_BH    (OFF_SXL + PLANE_A)          // 2 bufs x 2 planes
#define BUF_STRIDE (2 * PLANE_BB)
#define OFF_ENRM  (OFF_BH + 2 * BUF_STRIDE)    // 2 bufs x 256 B
#define OFF_SMIN  (OFF_ENRM + 512)             // 2 x 64 floats
#define OFF_SIMIN (OFF_SMIN + 512)             // 2 x 64 ints
#define OFF_SIDX  (OFF_SIMIN + 512)            // 64 ints
#define OFF_SRED  (OFF_SIDX + 256)             // 8 floats + flag
#define OFF_SCR   (OFF_ENRM)                   // finalize scratch (256 f)
#define SMEM_TOTAL (OFF_SRED + 64)             // ~57 KB -> 4 CTAs/SM

// device scratch (no allocations allowed)
__device__ float  g_enrm[K_CODES];
__device__ int    g_counts[K_CODES];
__device__ float  g_loss_partial[N_BLOCKS];
__device__ int    g_ticket;
__device__ __half g_eh[K_CODES * C_DIM];   // code-major [k][c]
__device__ __half g_el[K_CODES * C_DIM];

__device__ __forceinline__ uint32_t smem_u32(const void* p) {
    uint32_t a;
    asm("{ .reg .u64 t; cvta.to.shared.u64 t, %1; cvt.u32.u64 %0, t; }" : "=r"(a) : "l"(p));
    return a;
}
__device__ __forceinline__ void cp16(uint32_t dst, const void* src) {
    asm volatile("cp.async.cg.shared.global [%0], [%1], 16;" :: "r"(dst), "l"(src));
}
#define CP_COMMIT() asm volatile("cp.async.commit_group;" ::: "memory")
#define CP_WAIT(n)  asm volatile("cp.async.wait_group %0;" :: "n"(n) : "memory")

#define LDSM_X4(r0,r1,r2,r3,a) \
    asm volatile("ldmatrix.sync.aligned.m8n8.x4.shared.b16 {%0,%1,%2,%3}, [%4];" \
                 : "=r"(r0),"=r"(r1),"=r"(r2),"=r"(r3) : "r"(a))
#define MMA16816(c0,c1,c2,c3,a0,a1,a2,a3,b0,b1) \
    asm volatile("mma.sync.aligned.m16n8k16.row.col.f32.f16.f16.f32 " \
                 "{%0,%1,%2,%3}, {%4,%5,%6,%7}, {%8,%9}, {%0,%1,%2,%3};" \
                 : "+f"(c0),"+f"(c1),"+f"(c2),"+f"(c3) \
                 : "r"(a0),"r"(a1),"r"(a2),"r"(a3),"r"(b0),"r"(b1))

// ---------------------------------------------------------------------------
// Prep: smem-tiled transpose of embed -> fp16 hi/lo (code-major), ||e||^2,
// zero counts, reset ticket.  16 blocks x 256 threads.
// ---------------------------------------------------------------------------
__global__ __launch_bounds__(256) void vq_prep(const float* __restrict__ embed) {
    __shared__ float tile[64][65];
    __shared__ float nred[4][64];
    const int tid = threadIdx.x;
    const int k0 = blockIdx.x * 64;

    for (int i = tid; i < 4096; i += 256) {
        int c = i >> 6, kk = i & 63;
        tile[c][kk] = embed[c * K_CODES + k0 + kk];
    }
    __syncthreads();

    const int kk = tid & 63, part = tid >> 6;
    float s = 0.f;
    uint32_t hw[8], lw[8];
#pragma unroll
    for (int j = 0; j < 8; ++j) {
        int c0 = part * 16 + j * 2;
        float e0 = tile[c0][kk], e1 = tile[c0 + 1][kk];
        s += e0 * e0 + e1 * e1;
        __half h0 = __float2half_rn(e0), h1 = __float2half_rn(e1);
        __half l0 = __float2half_rn(e0 - __half2float(h0));
        __half l1 = __float2half_rn(e1 - __half2float(h1));
        hw[j] = (uint32_t)__half_as_ushort(h0) | ((uint32_t)__half_as_ushort(h1) << 16);
        lw[j] = (uint32_t)__half_as_ushort(l0) | ((uint32_t)__half_as_ushort(l1) << 16);
    }
    {
        uint4* dh = (uint4*)&g_eh[(k0 + kk) * C_DIM + part * 16];
        uint4* dl = (uint4*)&g_el[(k0 + kk) * C_DIM + part * 16];
        dh[0] = make_uint4(hw[0], hw[1], hw[2], hw[3]);
        dh[1] = make_uint4(hw[4], hw[5], hw[6], hw[7]);
        dl[0] = make_uint4(lw[0], lw[1], lw[2], lw[3]);
        dl[1] = make_uint4(lw[4], lw[5], lw[6], lw[7]);
    }
    nred[part][kk] = s;
    __syncthreads();
    if (part == 0) {
        g_enrm[k0 + kk] = nred[0][kk] + nred[1][kk] + nred[2][kk] + nred[3][kk];
        g_counts[k0 + kk] = 0;
    }
    if (blockIdx.x == 0 && tid == 0) g_ticket = 0;
}

// ---------------------------------------------------------------------------
// Main: 64-vector tiles, 512 CTAs (one full wave at 4 CTAs/SM).
// Warp (mw, kh): m-tile mw (16 rows), code half kh of each 64-code chunk.
// ---------------------------------------------------------------------------
__device__ __forceinline__ void load_chunk(int ck, int buf, uint32_t sb, int tid) {
    const __half* srch = g_eh + ck * CHUNK_K * C_DIM;
    const __half* srcl = g_el + ck * CHUNK_K * C_DIM;
    const uint32_t dbase = sb + OFF_BH + buf * BUF_STRIDE;
#pragma unroll
    for (int p = 0; p < 2; ++p) {
        int i = tid + p * 256;                  // granule 0..511
        int r = i >> 3, g = i & 7;
        uint32_t doff = (uint32_t)(r * PITCH_B + g * 16);
        cp16(dbase + doff,            srch + i * 8);
        cp16(dbase + PLANE_BB + doff, srcl + i * 8);
    }
    if (tid < 16)
        cp16(sb + OFF_ENRM + buf * 256 + tid * 16, g_enrm + ck * CHUNK_K + tid * 4);
    CP_COMMIT();
}

__global__ __launch_bounds__(256, 4) void vq_main(const float* __restrict__ inputs,
                                                  const float* __restrict__ embed,
                                                  float* __restrict__ out)
{
    extern __shared__ __align__(128) char smem[];
    const uint32_t sb = smem_u32(smem);
    const int tid = threadIdx.x;
    const int wid = tid >> 5, lane = tid & 31;
    const int mw = wid & 3, kh = wid >> 2;
    const int base_n = blockIdx.x * TILE_N;
    const int b = base_n >> 10, hw0 = base_n & 1023;

    float* smin  = (float*)(smem + OFF_SMIN);
    int*   simin = (int*)(smem + OFF_SIMIN);
    int*   sidx  = (int*)(smem + OFF_SIDX);
    float* sred  = (float*)(smem + OFF_SRED);

    load_chunk(0, 0, sb, tid);
    load_chunk(1, 1, sb, tid);

    // x tile -> fp16 hi/lo planes (row = vector nl, 64 rows)
    for (int idx = tid; idx < C_DIM * TILE_N; idx += 256) {
        int c = idx >> 6, nl = idx & 63;
        float x = inputs[b * 65536 + c * 1024 + hw0 + nl];
        __half xh = __float2half_rn(x);
        __half xl = __float2half_rn(x - __half2float(xh));
        *(__half*)(smem + OFF_SXH + nl * PITCH_B + c * 2) = xh;
        *(__half*)(smem + OFF_SXL + nl * PITCH_B + c * 2) = xl;
    }

    const uint32_t a_addr_h = sb + OFF_SXH + (mw * 16 + (lane & 15)) * PITCH_B
                            + (lane >> 4) * 16;
    const uint32_t a_addr_l = a_addr_h + (OFF_SXL - OFF_SXH);
    const int bm = lane >> 3, bsub = lane & 7;
    const uint32_t b_row_off = (uint32_t)(((bm >> 1) * 8 + bsub) * PITCH_B + (bm & 1) * 16);
    const int ntb = kh * 4;                   // this warp's 4 n-tiles per chunk

    float mind0 = 3.4e38f, mind1 = 3.4e38f;
    int   mini0 = 0,       mini1 = 0;

    for (int ck = 0; ck < N_CHUNKS; ++ck) {
        const int buf = ck & 1;
        if (ck == N_CHUNKS - 1) CP_WAIT(0); else CP_WAIT(1);
        __syncthreads();

        float acc[4][4];
#pragma unroll
        for (int t = 0; t < 4; ++t)
#pragma unroll
            for (int q = 0; q < 4; ++q) acc[t][q] = 0.f;

        const uint32_t bh_base = sb + OFF_BH + buf * BUF_STRIDE;
#pragma unroll
        for (int ks = 0; ks < 4; ++ks) {
            uint32_t ah0, ah1, ah2, ah3, al0, al1, al2, al3;
            LDSM_X4(ah0, ah1, ah2, ah3, a_addr_h + ks * 32);
            LDSM_X4(al0, al1, al2, al3, a_addr_l + ks * 32);
#pragma unroll
            for (int p = 0; p < 2; ++p) {
                const int t0 = p * 2;
                uint32_t bh0, bh1, bh2, bh3, bl0, bl1, bl2, bl3;
                uint32_t boff = (uint32_t)((ntb + t0) * 8 * PITCH_B) + b_row_off + ks * 32;
                LDSM_X4(bh0, bh1, bh2, bh3, bh_base + boff);
                LDSM_X4(bl0, bl1, bl2, bl3, bh_base + PLANE_BB + boff);
                MMA16816(acc[t0][0],acc[t0][1],acc[t0][2],acc[t0][3],
                         ah0,ah1,ah2,ah3, bh0,bh1);
                MMA16816(acc[t0+1][0],acc[t0+1][1],acc[t0+1][2],acc[t0+1][3],
                         ah0,ah1,ah2,ah3, bh2,bh3);
                MMA16816(acc[t0][0],acc[t0][1],acc[t0][2],acc[t0][3],
                         ah0,ah1,ah2,ah3, bl0,bl1);
                MMA16816(acc[t0+1][0],acc[t0+1][1],acc[t0+1][2],acc[t0+1][3],
                         ah0,ah1,ah2,ah3, bl2,bl3);
                MMA16816(acc[t0][0],acc[t0][1],acc[t0][2],acc[t0][3],
                         al0,al1,al2,al3, bh0,bh1);
                MMA16816(acc[t0+1][0],acc[t0+1][1],acc[t0+1][2],acc[t0+1][3],
                         al0,al1,al2,al3, bh2,bh3);
            }
        }

        // fused argmin over this warp's 32 codes of the chunk
        const float* senrm = (const float*)(smem + OFF_ENRM + buf * 256);
        const int k0c = ck * CHUNK_K;
#pragma unroll
        for (int t = 0; t < 4; ++t) {
            int kl = (ntb + t) * 8 + (lane & 3) * 2;
            float2 en = *(const float2*)(senrm + kl);
            float d0 = en.x - 2.f * acc[t][0];
            float d1 = en.y - 2.f * acc[t][1];
            float d2 = en.x - 2.f * acc[t][2];
            float d3 = en.y - 2.f * acc[t][3];
            int kc = k0c + kl;
            if (d0 < mind0) { mind0 = d0; mini0 = kc; }
            if (d1 < mind0) { mind0 = d1; mini0 = kc + 1; }
            if (d2 < mind1) { mind1 = d2; mini1 = kc; }
            if (d3 < mind1) { mind1 = d3; mini1 = kc + 1; }
        }
        __syncthreads();
        if (ck + 2 < N_CHUNKS) load_chunk(ck + 2, buf, sb, tid);
    }

    // reduce across the 4 lanes sharing each fragment row (tie-break: low idx)
#pragma unroll
    for (int m = 1; m < 4; m <<= 1) {
        float od = __shfl_xor_sync(0xFFFFFFFFu, mind0, m);
        int   oi = __shfl_xor_sync(0xFFFFFFFFu, mini0, m);
        if (od < mind0 || (od == mind0 && oi < mini0)) { mind0 = od; mini0 = oi; }
        od = __shfl_xor_sync(0xFFFFFFFFu, mind1, m);
        oi = __shfl_xor_sync(0xFFFFFFFFu, mini1, m);
        if (od < mind1 || (od == mind1 && oi < mini1)) { mind1 = od; mini1 = oi; }
    }
    if ((lane & 3) == 0) {
        int r0 = mw * 16 + (lane >> 2);
        int r1 = r0 + 8;
        smin[kh * 64 + r0]  = mind0;  simin[kh * 64 + r0] = mini0;
        smin[kh * 64 + r1]  = mind1;  simin[kh * 64 + r1] = mini1;
    }
    __syncthreads();

    // combine the two code halves per row (kh0 indices < kh1 -> tie keeps kh0)
    if (tid < TILE_N) {
        float da = smin[tid], db = smin[64 + tid];
        int   ia = simin[tid], ib = simin[64 + tid];
        int   fi = (db < da) ? ib : ia;
        sidx[tid] = fi;
        out[IDX_OFF + base_n + tid] = (float)fi;
        atomicAdd(&g_counts[fi], 1);
    }
    __syncthreads();

    // gather quantized, write coalesced, loss partial (deterministic order)
    float lsum = 0.f;
    for (int idx = tid; idx < C_DIM * TILE_N; idx += 256) {
        int c = idx >> 6, nl = idx & 63;
        int kq = sidx[nl];
        float q = __ldg(&embed[c * 1024 + kq]);
        float x = inputs[b * 65536 + c * 1024 + hw0 + nl];
        out[b * 65536 + c * 1024 + hw0 + nl] = q;
        float dv = q - x;
        lsum += dv * dv;
    }
#pragma unroll
    for (int m = 16; m > 0; m >>= 1) lsum += __shfl_xor_sync(0xFFFFFFFFu, lsum, m);
    if (lane == 0) sred[wid] = lsum;
    __syncthreads();
    if (tid == 0) {
        float s = 0.f;
#pragma unroll
        for (int w = 0; w < 8; ++w) s += sred[w];
        g_loss_partial[blockIdx.x] = s;
    }

    // ---- last-CTA finalize (loss + perplexity), deterministic trees ----
    __threadfence();
    __syncthreads();
    int* flag = (int*)(smem + OFF_SRED + 32);
    if (tid == 0) {
        int old = atomicAdd(&g_ticket, 1);
        *flag = (old == N_BLOCKS - 1);
    }
    __syncthreads();
    if (*flag) {
        __threadfence();
        float* scr = (float*)(smem + OFF_SCR);
        float ps = 0.f;
#pragma unroll
        for (int j = 0; j < 4; ++j) {
            int k = tid + j * 256;
            float p = (float)g_counts[k] * (1.f / 32768.f);
            ps += p * logf(p + 1e-10f);
        }
        scr[tid] = ps;
        __syncthreads();
        for (int s = 128; s > 0; s >>= 1) {
            if (tid < s) scr[tid] += scr[tid + s];
            __syncthreads();
        }
        if (tid == 0) out[PERP_OFF] = expf(-scr[0]);
        __syncthreads();
        scr[tid] = g_loss_partial[tid] + g_loss_partial[tid + 256];
        __syncthreads();
        for (int s = 128; s > 0; s >>= 1) {
            if (tid < s) scr[tid] += scr[tid + s];
            __syncthreads();
        }
        if (tid == 0) out[LOSS_OFF] = 0.25f * scr[0] / (float)Q_ELEMS;
    }
}

// ---------------------------------------------------------------------------
extern "C" void kernel_launch(void* const* d_in, const int* in_sizes, int n_in,
                              void* d_out, int out_size) {
    const float* inputs = (const float*)d_in[0];
    const float* embed  = (const float*)d_in[1];
    if (n_in >= 2 && in_sizes[0] == K_CODES * C_DIM && in_sizes[1] == Q_ELEMS) {
        const float* t = inputs; inputs = embed; embed = t;
    }
    float* out = (float*)d_out;

    static int smem_set = 0;
    if (!smem_set) {
        cudaFuncSetAttribute(vq_main, cudaFuncAttributeMaxDynamicSharedMemorySize,
                             SMEM_TOTAL);
        smem_set = 1;
    }

    vq_prep<<<16, 256>>>(embed);
    vq_main<<<N_BLOCKS, 256, SMEM_TOTAL>>>(inputs, embed, out);
}

// round 8
// speedup vs baseline: 1.0878x; 1.0878x over previous
#include <cuda_runtime.h>
#include <cuda_fp16.h>
#include <math.h>
#include <stdint.h>

#define K_CODES 1024
#define C_DIM   64
#define N_TOT   32768
#define TILE_N  128
#define CHUNK_K 128
#define N_CHUNKS 8
#define N_BLOCKS (N_TOT / TILE_N)   // 256

#define Q_ELEMS  (32*64*32*32)      // 2097152
#define LOSS_OFF Q_ELEMS
#define IDX_OFF  (Q_ELEMS + 1)
#define PERP_OFF (Q_ELEMS + 1 + N_TOT)

#define PITCH_B   144               // 9 x 16B: conflict-free ldmatrix rows
#define PLANE_B   18432             // 128 rows x 144 B

// smem layout (dynamic)
#define OFF_SXH   0
#define OFF_SXL   (OFF_SXH + PLANE_B)
#define OFF_BH    (OFF_SXL + PLANE_B)        // 2 bufs x (hi plane + lo plane)
#define BUF_STRIDE (2 * PLANE_B)
#define OFF_ENRM  (OFF_BH + 2 * BUF_STRIDE)  // 2 bufs x 512 B
#define OFF_SMIN  (OFF_ENRM + 1024)          // 2 x 128 floats
#define OFF_SIMIN (OFF_SMIN + 1024)          // 2 x 128 ints
#define OFF_SIDX  (OFF_SIMIN + 1024)         // 128 ints
#define OFF_SRED  (OFF_SIDX + 512)           // 8 floats + flag
#define OFF_SCR   (OFF_ENRM)                 // finalize scratch (256 f)
#define SMEM_TOTAL (OFF_SRED + 64)           // ~114 KB -> 2 CTAs/SM

// device scratch (no allocations allowed)
__device__ float  g_enrm[K_CODES];
__device__ int    g_counts[K_CODES];
__device__ float  g_loss_partial[N_BLOCKS];
__device__ int    g_ticket;
__device__ __half g_eh[K_CODES * C_DIM];   // code-major [k][c]
__device__ __half g_el[K_CODES * C_DIM];

__device__ __forceinline__ uint32_t smem_u32(const void* p) {
    uint32_t a;
    asm("{ .reg .u64 t; cvta.to.shared.u64 t, %1; cvt.u32.u64 %0, t; }" : "=r"(a) : "l"(p));
    return a;
}
__device__ __forceinline__ void cp16(uint32_t dst, const void* src) {
    asm volatile("cp.async.cg.shared.global [%0], [%1], 16;" :: "r"(dst), "l"(src));
}
#define CP_COMMIT() asm volatile("cp.async.commit_group;" ::: "memory")
#define CP_WAIT(n)  asm volatile("cp.async.wait_group %0;" :: "n"(n) : "memory")

#define LDSM_X4(r0,r1,r2,r3,a) \
    asm volatile("ldmatrix.sync.aligned.m8n8.x4.shared.b16 {%0,%1,%2,%3}, [%4];" \
                 : "=r"(r0),"=r"(r1),"=r"(r2),"=r"(r3) : "r"(a))
#define MMA16816(c0,c1,c2,c3,a0,a1,a2,a3,b0,b1) \
    asm volatile("mma.sync.aligned.m16n8k16.row.col.f32.f16.f16.f32 " \
                 "{%0,%1,%2,%3}, {%4,%5,%6,%7}, {%8,%9}, {%0,%1,%2,%3};" \
                 : "+f"(c0),"+f"(c1),"+f"(c2),"+f"(c3) \
                 : "r"(a0),"r"(a1),"r"(a2),"r"(a3),"r"(b0),"r"(b1))

// ---------------------------------------------------------------------------
// Prep: smem-tiled transpose of embed -> fp16 hi/lo (code-major), ||e||^2,
// zero counts, reset ticket.  16 blocks x 256 threads.
// ---------------------------------------------------------------------------
__global__ __launch_bounds__(256) void vq_prep(const float* __restrict__ embed) {
    __shared__ float tile[64][65];
    __shared__ float nred[4][64];
    const int tid = threadIdx.x;
    const int k0 = blockIdx.x * 64;

    for (int i = tid; i < 4096; i += 256) {
        int c = i >> 6, kk = i & 63;
        tile[c][kk] = embed[c * K_CODES + k0 + kk];
    }
    __syncthreads();

    const int kk = tid & 63, part = tid >> 6;
    float s = 0.f;
    uint32_t hw[8], lw[8];
#pragma unroll
    for (int j = 0; j < 8; ++j) {
        int c0 = part * 16 + j * 2;
        float e0 = tile[c0][kk], e1 = tile[c0 + 1][kk];
        s += e0 * e0 + e1 * e1;
        __half h0 = __float2half_rn(e0), h1 = __float2half_rn(e1);
        __half l0 = __float2half_rn(e0 - __half2float(h0));
        __half l1 = __float2half_rn(e1 - __half2float(h1));
        hw[j] = (uint32_t)__half_as_ushort(h0) | ((uint32_t)__half_as_ushort(h1) << 16);
        lw[j] = (uint32_t)__half_as_ushort(l0) | ((uint32_t)__half_as_ushort(l1) << 16);
    }
    {
        uint4* dh = (uint4*)&g_eh[(k0 + kk) * C_DIM + part * 16];
        uint4* dl = (uint4*)&g_el[(k0 + kk) * C_DIM + part * 16];
        dh[0] = make_uint4(hw[0], hw[1], hw[2], hw[3]);
        dh[1] = make_uint4(hw[4], hw[5], hw[6], hw[7]);
        dl[0] = make_uint4(lw[0], lw[1], lw[2], lw[3]);
        dl[1] = make_uint4(lw[4], lw[5], lw[6], lw[7]);
    }
    nred[part][kk] = s;
    __syncthreads();
    if (part == 0) {
        g_enrm[k0 + kk] = nred[0][kk] + nred[1][kk] + nred[2][kk] + nred[3][kk];
        g_counts[k0 + kk] = 0;
    }
    if (blockIdx.x == 0 && tid == 0) g_ticket = 0;
}

// ---------------------------------------------------------------------------
// Main: warp = 2 m-tiles x 8 n-tiles (LDSM:MMA = 1:4), cp.async double-buffered
// B, fused argmin + gather + loss; last CTA finalizes loss/perplexity.
// ---------------------------------------------------------------------------
__device__ __forceinline__ void load_chunk(int ck, int buf, uint32_t sb, int tid) {
    const __half* srch = g_eh + ck * CHUNK_K * C_DIM;
    const __half* srcl = g_el + ck * CHUNK_K * C_DIM;
    const uint32_t dbase = sb + OFF_BH + buf * BUF_STRIDE;
#pragma unroll
    for (int p = 0; p < 4; ++p) {
        int i = tid + p * 256;                  // granule id 0..1023
        int r = i >> 3, g = i & 7;
        uint32_t doff = (uint32_t)(r * PITCH_B + g * 16);
        cp16(dbase + doff,           srch + i * 8);
        cp16(dbase + PLANE_B + doff, srcl + i * 8);
    }
    if (tid < 32)
        cp16(sb + OFF_ENRM + buf * 512 + tid * 16, g_enrm + ck * CHUNK_K + tid * 4);
    CP_COMMIT();
}

__global__ __launch_bounds__(256, 2) void vq_main(const float* __restrict__ inputs,
                                                  const float* __restrict__ embed,
                                                  float* __restrict__ out)
{
    extern __shared__ __align__(128) char smem[];
    const uint32_t sb = smem_u32(smem);
    const int tid = threadIdx.x;
    const int wid = tid >> 5, lane = tid & 31;
    const int mw = wid & 3, nh = wid >> 2;     // m32 block, n-half of chunk
    const int base_n = blockIdx.x * TILE_N;
    const int b = base_n >> 10, hw0 = base_n & 1023;

    float* smin  = (float*)(smem + OFF_SMIN);
    int*   simin = (int*)(smem + OFF_SIMIN);
    int*   sidx  = (int*)(smem + OFF_SIDX);
    float* sred  = (float*)(smem + OFF_SRED);

    load_chunk(0, 0, sb, tid);
    load_chunk(1, 1, sb, tid);

    // x tile -> fp16 hi/lo planes (row = vector nl, 128 rows)
    for (int idx = tid; idx < C_DIM * TILE_N; idx += 256) {
        int c = idx >> 7, nl = idx & 127;
        float x = inputs[b * 65536 + c * 1024 + hw0 + nl];
        __half xh = __float2half_rn(x);
        __half xl = __float2half_rn(x - __half2float(xh));
        *(__half*)(smem + OFF_SXH + nl * PITCH_B + c * 2) = xh;
        *(__half*)(smem + OFF_SXL + nl * PITCH_B + c * 2) = xl;
    }

    // A addresses: warp owns rows [mw*32, mw*32+32) = 2 m-tiles
    const uint32_t a_addr_h = sb + OFF_SXH + (mw * 32 + (lane & 15)) * PITCH_B
                            + (lane >> 4) * 16;
    const uint32_t a_addr_l = a_addr_h + (OFF_SXL - OFF_SXH);
    const int bm = lane >> 3, bsub = lane & 7;
    const uint32_t b_row_off = (uint32_t)(((bm >> 1) * 8 + bsub) * PITCH_B + (bm & 1) * 16);
    const int ntb = nh * 8;                    // warp's 8 n-tiles within chunk

    float mind[2][2] = {{3.4e38f, 3.4e38f}, {3.4e38f, 3.4e38f}};
    int   mini[2][2] = {{0, 0}, {0, 0}};

    for (int ck = 0; ck < N_CHUNKS; ++ck) {
        const int buf = ck & 1;
        if (ck == N_CHUNKS - 1) CP_WAIT(0); else CP_WAIT(1);
        __syncthreads();

        float acc[2][8][4];
#pragma unroll
        for (int m = 0; m < 2; ++m)
#pragma unroll
            for (int t = 0; t < 8; ++t)
#pragma unroll
                for (int q = 0; q < 4; ++q) acc[m][t][q] = 0.f;

        const uint32_t bh_base = sb + OFF_BH + buf * BUF_STRIDE;
#pragma unroll
        for (int ks = 0; ks < 4; ++ks) {
            uint32_t ah[2][4], al[2][4];
#pragma unroll
            for (int m = 0; m < 2; ++m) {
                LDSM_X4(ah[m][0], ah[m][1], ah[m][2], ah[m][3],
                        a_addr_h + m * 16 * PITCH_B + ks * 32);
                LDSM_X4(al[m][0], al[m][1], al[m][2], al[m][3],
                        a_addr_l + m * 16 * PITCH_B + ks * 32);
            }
#pragma unroll
            for (int p = 0; p < 4; ++p) {
                const int t0 = p * 2;
                uint32_t bh0, bh1, bh2, bh3, bl0, bl1, bl2, bl3;
                uint32_t boff = (uint32_t)((ntb + t0) * 8 * PITCH_B) + b_row_off + ks * 32;
                LDSM_X4(bh0, bh1, bh2, bh3, bh_base + boff);
                LDSM_X4(bl0, bl1, bl2, bl3, bh_base + PLANE_B + boff);
                // term hh (4 independent accs), then hl, then lh
#pragma unroll
                for (int m = 0; m < 2; ++m) {
                    MMA16816(acc[m][t0][0],acc[m][t0][1],acc[m][t0][2],acc[m][t0][3],
                             ah[m][0],ah[m][1],ah[m][2],ah[m][3], bh0,bh1);
                    MMA16816(acc[m][t0+1][0],acc[m][t0+1][1],acc[m][t0+1][2],acc[m][t0+1][3],
                             ah[m][0],ah[m][1],ah[m][2],ah[m][3], bh2,bh3);
                }
#pragma unroll
                for (int m = 0; m < 2; ++m) {
                    MMA16816(acc[m][t0][0],acc[m][t0][1],acc[m][t0][2],acc[m][t0][3],
                             ah[m][0],ah[m][1],ah[m][2],ah[m][3], bl0,bl1);
                    MMA16816(acc[m][t0+1][0],acc[m][t0+1][1],acc[m][t0+1][2],acc[m][t0+1][3],
                             ah[m][0],ah[m][1],ah[m][2],ah[m][3], bl2,bl3);
                }
#pragma unroll
                for (int m = 0; m < 2; ++m) {
                    MMA16816(acc[m][t0][0],acc[m][t0][1],acc[m][t0][2],acc[m][t0][3],
                             al[m][0],al[m][1],al[m][2],al[m][3], bh0,bh1);
                    MMA16816(acc[m][t0+1][0],acc[m][t0+1][1],acc[m][t0+1][2],acc[m][t0+1][3],
                             al[m][0],al[m][1],al[m][2],al[m][3], bh2,bh3);
                }
            }
        }

        // fused argmin over this warp's 64 codes of the chunk
        const float* senrm = (const float*)(smem + OFF_ENRM + buf * 512);
        const int k0c = ck * CHUNK_K;
#pragma unroll
        for (int t = 0; t < 8; ++t) {
            int kl = (ntb + t) * 8 + (lane & 3) * 2;
            float2 en = *(const float2*)(senrm + kl);
            int kc = k0c + kl;
#pragma unroll
            for (int m = 0; m < 2; ++m) {
                float d0 = en.x - 2.f * acc[m][t][0];
                float d1 = en.y - 2.f * acc[m][t][1];
                float d2 = en.x - 2.f * acc[m][t][2];
                float d3 = en.y - 2.f * acc[m][t][3];
                if (d0 < mind[m][0]) { mind[m][0] = d0; mini[m][0] = kc; }
                if (d1 < mind[m][0]) { mind[m][0] = d1; mini[m][0] = kc + 1; }
                if (d2 < mind[m][1]) { mind[m][1] = d2; mini[m][1] = kc; }
                if (d3 < mind[m][1]) { mind[m][1] = d3; mini[m][1] = kc + 1; }
            }
        }
        __syncthreads();
        if (ck + 2 < N_CHUNKS) load_chunk(ck + 2, buf, sb, tid);
    }

    // reduce across the 4 lanes sharing each fragment row (tie-break: low idx)
#pragma unroll
    for (int m = 0; m < 2; ++m)
#pragma unroll
        for (int h = 0; h < 2; ++h) {
#pragma unroll
            for (int s = 1; s < 4; s <<= 1) {
                float od = __shfl_xor_sync(0xFFFFFFFFu, mind[m][h], s);
                int   oi = __shfl_xor_sync(0xFFFFFFFFu, mini[m][h], s);
                if (od < mind[m][h] || (od == mind[m][h] && oi < mini[m][h])) {
                    mind[m][h] = od; mini[m][h] = oi;
                }
            }
        }
    if ((lane & 3) == 0) {
#pragma unroll
        for (int m = 0; m < 2; ++m) {
            int r0 = mw * 32 + m * 16 + (lane >> 2);
            smin[nh * 128 + r0]     = mind[m][0];  simin[nh * 128 + r0]     = mini[m][0];
            smin[nh * 128 + r0 + 8] = mind[m][1];  simin[nh * 128 + r0 + 8] = mini[m][1];
        }
    }
    __syncthreads();

    // combine the two code-half warps per row (exact low-index tie-break)
    if (tid < TILE_N) {
        float da = smin[tid], db = smin[128 + tid];
        int   ia = simin[tid], ib = simin[128 + tid];
        int   fi = (db < da || (db == da && ib < ia)) ? ib : ia;
        sidx[tid] = fi;
        out[IDX_OFF + base_n + tid] = (float)fi;
        atomicAdd(&g_counts[fi], 1);
    }
    __syncthreads();

    // gather quantized, write coalesced, loss partial (deterministic order)
    float lsum = 0.f;
    for (int idx = tid; idx < C_DIM * TILE_N; idx += 256) {
        int c = idx >> 7, nl = idx & 127;
        int kq = sidx[nl];
        float q = __ldg(&embed[c * 1024 + kq]);
        float x = inputs[b * 65536 + c * 1024 + hw0 + nl];
        out[b * 65536 + c * 1024 + hw0 + nl] = q;
        float dv = q - x;
        lsum += dv * dv;
    }
#pragma unroll
    for (int s = 16; s > 0; s >>= 1) lsum += __shfl_xor_sync(0xFFFFFFFFu, lsum, s);
    if (lane == 0) sred[wid] = lsum;
    __syncthreads();
    if (tid == 0) {
        float s = 0.f;
#pragma unroll
        for (int w = 0; w < 8; ++w) s += sred[w];
        g_loss_partial[blockIdx.x] = s;
    }

    // ---- last-CTA finalize (loss + perplexity), deterministic trees ----
    __threadfence();
    __syncthreads();
    int* flag = (int*)(smem + OFF_SRED + 32);
    if (tid == 0) {
        int old = atomicAdd(&g_ticket, 1);
        *flag = (old == N_BLOCKS - 1);
    }
    __syncthreads();
    if (*flag) {
        __threadfence();
        float* scr = (float*)(smem + OFF_SCR);
        float ps = 0.f;
#pragma unroll
        for (int j = 0; j < 4; ++j) {
            int k = tid + j * 256;
            float p = (float)g_counts[k] * (1.f / 32768.f);
            ps += p * logf(p + 1e-10f);
        }
        scr[tid] = ps;
        __syncthreads();
        for (int s = 128; s > 0; s >>= 1) {
            if (tid < s) scr[tid] += scr[tid + s];
            __syncthreads();
        }
        if (tid == 0) out[PERP_OFF] = expf(-scr[0]);
        __syncthreads();
        scr[tid] = g_loss_partial[tid];
        __syncthreads();
        for (int s = 128; s > 0; s >>= 1) {
            if (tid < s) scr[tid] += scr[tid + s];
            __syncthreads();
        }
        if (tid == 0) out[LOSS_OFF] = 0.25f * scr[0] / (float)Q_ELEMS;
    }
}

// ---------------------------------------------------------------------------
extern "C" void kernel_launch(void* const* d_in, const int* in_sizes, int n_in,
                              void* d_out, int out_size) {
    const float* inputs = (const float*)d_in[0];
    const float* embed  = (const float*)d_in[1];
    if (n_in >= 2 && in_sizes[0] == K_CODES * C_DIM && in_sizes[1] == Q_ELEMS) {
        const float* t = inputs; inputs = embed; embed = t;
    }
    float* out = (float*)d_out;

    static int smem_set = 0;
    if (!smem_set) {
        cudaFuncSetAttribute(vq_main, cudaFuncAttributeMaxDynamicSharedMemorySize,
                             SMEM_TOTAL);
        smem_set = 1;
    }

    vq_prep<<<16, 256>>>(embed);
    vq_main<<<N_BLOCKS, 256, SMEM_TOTAL>>>(inputs, embed, out);
}